// round 2
// baseline (speedup 1.0000x reference)
#include <cuda_runtime.h>

#define NN 100000
#define EE 1600000
#define MM (EE + NN)
#define HH 64

// ---------------- scratch (__device__ globals: allocation-free) ----------------
__device__ float4 g_h4[NN * 16];     // h  [N,64]
__device__ float4 g_agg4[NN * 16];   // GCN shared aggregation  sum norm*h[row]
__device__ float4 g_acc4[NN * 16];   // AGNN numerator          sum e*h[row]
__device__ float  g_xproj[NN * HH];  // tanh(h@wx+bx)
__device__ float  g_inn[NN];         // 1/(||h||+eps)
__device__ float  g_deg[NN];
__device__ float  g_dinv[NN];
__device__ float  g_s[NN];           // AGNN softmax denominator

// ---------------- small kernels ----------------
__global__ void k_init() {
    int i = blockIdx.x * blockDim.x + threadIdx.x;
    if (i < NN * HH) {
        ((float*)g_agg4)[i] = 0.f;
        ((float*)g_acc4)[i] = 0.f;
    }
    if (i < NN) { g_deg[i] = 1.0f; g_s[i] = 0.f; }   // deg starts at 1 (self-loop)
}

__global__ void k_deg(const int* __restrict__ ei) {
    int e = blockIdx.x * blockDim.x + threadIdx.x;
    if (e < EE) {
        int c = ei[EE + e];
        atomicAdd(&g_deg[c], 1.0f);
    }
}

__global__ void k_dinv() {
    int i = blockIdx.x * blockDim.x + threadIdx.x;
    if (i < NN) g_dinv[i] = rsqrtf(g_deg[i]);        // deg >= 1 always
}

// ---------------- 64x64 tile GEMM helper (64 nodes/block, 256 thr, 4x4 blocking) ----
// inS/outS tiles are [64][65] (pad 65 to kill bank conflicts). wS is [64][64] row-major.
// ACT: 0 none, 1 relu, 2 tanh
template <int ACT>
__device__ __forceinline__ void mm64(const float* __restrict__ inS,
                                     const float* __restrict__ wS,
                                     const float* __restrict__ bS,
                                     float* __restrict__ outS, int t) {
    const int jt = (t & 15) * 4;
    const int rt = (t >> 4) * 4;
    float acc[4][4];
#pragma unroll
    for (int i = 0; i < 4; i++)
#pragma unroll
        for (int q = 0; q < 4; q++) acc[i][q] = 0.f;
#pragma unroll 8
    for (int k = 0; k < 64; k++) {
        float4 wv = *reinterpret_cast<const float4*>(wS + (k << 6) + jt);
#pragma unroll
        for (int i = 0; i < 4; i++) {
            float xv = inS[(rt + i) * 65 + k];
            acc[i][0] = fmaf(xv, wv.x, acc[i][0]);
            acc[i][1] = fmaf(xv, wv.y, acc[i][1]);
            acc[i][2] = fmaf(xv, wv.z, acc[i][2]);
            acc[i][3] = fmaf(xv, wv.w, acc[i][3]);
        }
    }
#pragma unroll
    for (int i = 0; i < 4; i++)
#pragma unroll
        for (int q = 0; q < 4; q++) {
            float v = acc[i][q] + bS[jt + q];
            if (ACT == 1) v = fmaxf(v, 0.f);
            if (ACT == 2) v = tanhf(v);
            outS[(rt + i) * 65 + jt + q] = v;
        }
}

// ---------------- fused input MLP + xproj + inv-norm ----------------
// smem: w1|w2|w3|wx (4*4096) + biases(256) + tA(4160) + tB(4160) = 24960 floats
#define SMEM_MLP_FLOATS 24960
__global__ void __launch_bounds__(256) k_mlp(
    const float* __restrict__ x,
    const float* __restrict__ w1, const float* __restrict__ b1,
    const float* __restrict__ w2, const float* __restrict__ b2,
    const float* __restrict__ w3, const float* __restrict__ b3,
    const float* __restrict__ wx, const float* __restrict__ bx) {
    extern __shared__ float sm[];
    float* w1s = sm;
    float* w2s = sm + 4096;
    float* w3s = sm + 8192;
    float* wxs = sm + 12288;
    float* bs  = sm + 16384;   // b1|b2|b3|bx
    float* tA  = sm + 16640;
    float* tB  = sm + 20800;
    int t = threadIdx.x;
    for (int i = t; i < 4096; i += 256) {
        w1s[i] = w1[i]; w2s[i] = w2[i]; w3s[i] = w3[i]; wxs[i] = wx[i];
    }
    if (t < 64) { bs[t] = b1[t]; bs[64 + t] = b2[t]; bs[128 + t] = b3[t]; bs[192 + t] = bx[t]; }
    int n0 = blockIdx.x * 64;
    for (int i = t; i < 4096; i += 256) {
        int r = i >> 6, k = i & 63;
        int n = n0 + r;
        tA[r * 65 + k] = (n < NN) ? x[n * 64 + k] : 0.f;
    }
    __syncthreads();
    mm64<1>(tA, w1s, bs, tB, t);       __syncthreads();
    mm64<1>(tB, w2s, bs + 64, tA, t);  __syncthreads();
    mm64<0>(tA, w3s, bs + 128, tB, t); __syncthreads();   // h in tB
    // store h + inverse norm
    float* gh = (float*)g_h4;
    for (int i = t; i < 4096; i += 256) {
        int r = i >> 6, k = i & 63;
        int n = n0 + r;
        if (n < NN) gh[n * 64 + k] = tB[r * 65 + k];
    }
    if (t < 64) {
        int n = n0 + t;
        if (n < NN) {
            float ss = 0.f;
#pragma unroll 8
            for (int k = 0; k < 64; k++) { float v = tB[t * 65 + k]; ss = fmaf(v, v, ss); }
            g_inn[n] = 1.f / (sqrtf(ss) + 1e-12f);
        }
    }
    __syncthreads();
    mm64<2>(tB, wxs, bs + 192, tA, t); __syncthreads();   // xproj in tA
    for (int i = t; i < 4096; i += 256) {
        int r = i >> 6, k = i & 63;
        int n = n0 + r;
        if (n < NN) g_xproj[n * 64 + k] = tA[r * 65 + k];
    }
}

// ---------------- single fused edge pass (16 lanes / edge, float4 vector REDs) ------
// agg[c]  += dinv[r]*dinv[c] * h[r]
// acc1[c] += exp(beta * h[r].h[c] * inn[r]*inn[c]) * h[r]
// s[c]    += exp(...)
__global__ void __launch_bounds__(256) k_edge(const int* __restrict__ ei,
                                              const float* __restrict__ betap) {
    int gid = blockIdx.x * 256 + threadIdx.x;
    int e = gid >> 4;
    if (e >= MM) return;
    int l = gid & 15;
    int r, c;
    if (e < EE) {
        r = ei[e];
        c = ei[EE + e];
    } else {
        r = e - EE; c = r;          // self-loop
    }
    float4 hr = g_h4[r * 16 + l];
    float4 hc = (r == c) ? hr : g_h4[c * 16 + l];
    float dp = hr.x * hc.x + hr.y * hc.y + hr.z * hc.z + hr.w * hc.w;
    dp += __shfl_xor_sync(0xFFFFFFFFu, dp, 8);
    dp += __shfl_xor_sync(0xFFFFFFFFu, dp, 4);
    dp += __shfl_xor_sync(0xFFFFFFFFu, dp, 2);
    dp += __shfl_xor_sync(0xFFFFFFFFu, dp, 1);
    float alpha = (*betap) * dp * g_inn[r] * g_inn[c];   // |alpha| <= |beta|: exp safe
    float ev = expf(alpha);
    float nm = g_dinv[r] * g_dinv[c];
    float4 av = make_float4(nm * hr.x, nm * hr.y, nm * hr.z, nm * hr.w);
    float4 e4 = make_float4(ev * hr.x, ev * hr.y, ev * hr.z, ev * hr.w);
    atomicAdd(&g_agg4[c * 16 + l], av);
    atomicAdd(&g_acc4[c * 16 + l], e4);
    if (l == 0) atomicAdd(&g_s[c], ev);
}

// ---------------- fused filters + attention fusion + classifier ----------------
// f0 = agg@wg1+bg1 ; f1 = agg@wg2+bg2 ; hp_k = tanh(f_k@wf+bf)
// logit_k = hp_k . xproj ; score = softmax ; res = s0*f0+s1*f1 ; h1 = acc1/s
// y = [res, h1] @ wc + bc
#define SMEM_FIN_FLOATS 31684
__global__ void __launch_bounds__(256) k_final(
    const float* __restrict__ wg1, const float* __restrict__ bg1,
    const float* __restrict__ wg2, const float* __restrict__ bg2,
    const float* __restrict__ wf,  const float* __restrict__ bf,
    const float* __restrict__ wc,  const float* __restrict__ bc,
    float* __restrict__ out) {
    extern __shared__ float sm[];
    float* wg1s = sm;
    float* wg2s = sm + 4096;
    float* wfs  = sm + 8192;
    float* wcs  = sm + 12288;   // 256
    float* bg1s = sm + 12544;
    float* bg2s = sm + 12608;
    float* bfs  = sm + 12672;
    float* bcs  = sm + 12736;   // 2 (+2 pad)
    float* aggS = sm + 12740;   // 4160
    float* xpS  = sm + 16900;   // 4160
    float* f0S  = sm + 21060;   // 4160
    float* f1S  = sm + 25220;   // 4160
    float* red0 = sm + 29380;   // 64*17
    float* red1 = sm + 30468;   // 64*17
    float* sc0  = sm + 31556;   // 64
    float* sc1  = sm + 31620;   // 64
    int t = threadIdx.x;
    for (int i = t; i < 4096; i += 256) { wg1s[i] = wg1[i]; wg2s[i] = wg2[i]; wfs[i] = wf[i]; }
    if (t < 256) wcs[t] = wc[t];
    if (t < 64) { bg1s[t] = bg1[t]; bg2s[t] = bg2[t]; bfs[t] = bf[t]; }
    if (t < 2) bcs[t] = bc[t];
    int n0 = blockIdx.x * 64;
    const float* agg = (const float*)g_agg4;
    for (int i = t; i < 4096; i += 256) {
        int r = i >> 6, k = i & 63;
        int n = n0 + r;
        aggS[r * 65 + k] = (n < NN) ? agg[n * 64 + k] : 0.f;
        xpS[r * 65 + k]  = (n < NN) ? g_xproj[n * 64 + k] : 0.f;
    }
    __syncthreads();
    const int jt = (t & 15) * 4;
    const int rt = (t >> 4) * 4;
    float f0r[4][4], f1r[4][4];
    {
        float a0[4][4] = {}, a1[4][4] = {};
#pragma unroll 4
        for (int k = 0; k < 64; k++) {
            float4 w1v = *(const float4*)(wg1s + (k << 6) + jt);
            float4 w2v = *(const float4*)(wg2s + (k << 6) + jt);
#pragma unroll
            for (int i = 0; i < 4; i++) {
                float xv = aggS[(rt + i) * 65 + k];
                a0[i][0] = fmaf(xv, w1v.x, a0[i][0]);
                a0[i][1] = fmaf(xv, w1v.y, a0[i][1]);
                a0[i][2] = fmaf(xv, w1v.z, a0[i][2]);
                a0[i][3] = fmaf(xv, w1v.w, a0[i][3]);
                a1[i][0] = fmaf(xv, w2v.x, a1[i][0]);
                a1[i][1] = fmaf(xv, w2v.y, a1[i][1]);
                a1[i][2] = fmaf(xv, w2v.z, a1[i][2]);
                a1[i][3] = fmaf(xv, w2v.w, a1[i][3]);
            }
        }
#pragma unroll
        for (int i = 0; i < 4; i++)
#pragma unroll
            for (int q = 0; q < 4; q++) {
                f0r[i][q] = a0[i][q] + bg1s[jt + q];
                f1r[i][q] = a1[i][q] + bg2s[jt + q];
                f0S[(rt + i) * 65 + jt + q] = f0r[i][q];
                f1S[(rt + i) * 65 + jt + q] = f1r[i][q];
            }
    }
    __syncthreads();
    // hp matmuls + fused dot with xproj
    float p0[4] = {0, 0, 0, 0}, p1[4] = {0, 0, 0, 0};
    {
        float a0[4][4] = {}, a1[4][4] = {};
#pragma unroll 4
        for (int k = 0; k < 64; k++) {
            float4 wv = *(const float4*)(wfs + (k << 6) + jt);
#pragma unroll
            for (int i = 0; i < 4; i++) {
                float x0 = f0S[(rt + i) * 65 + k];
                float x1 = f1S[(rt + i) * 65 + k];
                a0[i][0] = fmaf(x0, wv.x, a0[i][0]);
                a0[i][1] = fmaf(x0, wv.y, a0[i][1]);
                a0[i][2] = fmaf(x0, wv.z, a0[i][2]);
                a0[i][3] = fmaf(x0, wv.w, a0[i][3]);
                a1[i][0] = fmaf(x1, wv.x, a1[i][0]);
                a1[i][1] = fmaf(x1, wv.y, a1[i][1]);
                a1[i][2] = fmaf(x1, wv.z, a1[i][2]);
                a1[i][3] = fmaf(x1, wv.w, a1[i][3]);
            }
        }
#pragma unroll
        for (int i = 0; i < 4; i++)
#pragma unroll
            for (int q = 0; q < 4; q++) {
                float hp0 = tanhf(a0[i][q] + bfs[jt + q]);
                float hp1 = tanhf(a1[i][q] + bfs[jt + q]);
                float xp = xpS[(rt + i) * 65 + jt + q];
                p0[i] = fmaf(hp0, xp, p0[i]);
                p1[i] = fmaf(hp1, xp, p1[i]);
            }
    }
#pragma unroll
    for (int i = 0; i < 4; i++) {
        red0[(rt + i) * 17 + (t & 15)] = p0[i];
        red1[(rt + i) * 17 + (t & 15)] = p1[i];
    }
    __syncthreads();
    if (t < 64) {
        float l0 = 0.f, l1 = 0.f;
#pragma unroll
        for (int m = 0; m < 16; m++) { l0 += red0[t * 17 + m]; l1 += red1[t * 17 + m]; }
        float mx = fmaxf(l0, l1);
        float e0 = expf(l0 - mx), e1 = expf(l1 - mx);
        float inv = 1.f / (e0 + e1);
        sc0[t] = e0 * inv;
        sc1[t] = e1 * inv;
    }
    __syncthreads();
    const float* acc1 = (const float*)g_acc4;
#pragma unroll
    for (int i = 0; i < 4; i++) {
        int rr = rt + i;
        int n = n0 + rr;
        float y0 = 0.f, y1 = 0.f;
        if (n < NN) {
            float s0 = sc0[rr], s1 = sc1[rr];
            float invs = 1.f / g_s[n];
            float4 hv = *(const float4*)(acc1 + n * 64 + jt);
            float h1v[4] = {hv.x * invs, hv.y * invs, hv.z * invs, hv.w * invs};
#pragma unroll
            for (int q = 0; q < 4; q++) {
                float res = s0 * f0r[i][q] + s1 * f1r[i][q];
                int j = jt + q;
                y0 += res * wcs[j * 2 + 0] + h1v[q] * wcs[(64 + j) * 2 + 0];
                y1 += res * wcs[j * 2 + 1] + h1v[q] * wcs[(64 + j) * 2 + 1];
            }
        }
        red0[rr * 17 + (t & 15)] = y0;
        red1[rr * 17 + (t & 15)] = y1;
    }
    __syncthreads();
    if (t < 64) {
        int n = n0 + t;
        if (n < NN) {
            float y0 = bcs[0], y1 = bcs[1];
#pragma unroll
            for (int m = 0; m < 16; m++) { y0 += red0[t * 17 + m]; y1 += red1[t * 17 + m]; }
            out[n * 2 + 0] = y0;
            out[n * 2 + 1] = y1;
        }
    }
}

// ---------------- launch ----------------
extern "C" void kernel_launch(void* const* d_in, const int* in_sizes, int n_in,
                              void* d_out, int out_size) {
    const float* x   = (const float*)d_in[0];
    const int*   ei  = (const int*)d_in[1];      // JAX demotes int64 -> int32
    const float* w1  = (const float*)d_in[2];
    const float* b1  = (const float*)d_in[3];
    const float* w2  = (const float*)d_in[4];
    const float* b2  = (const float*)d_in[5];
    const float* w3  = (const float*)d_in[6];
    const float* b3  = (const float*)d_in[7];
    const float* wg1 = (const float*)d_in[8];
    const float* bg1 = (const float*)d_in[9];
    const float* wg2 = (const float*)d_in[10];
    const float* bg2 = (const float*)d_in[11];
    const float* beta= (const float*)d_in[12];
    const float* wf  = (const float*)d_in[13];
    const float* bf  = (const float*)d_in[14];
    const float* wx  = (const float*)d_in[15];
    const float* bx  = (const float*)d_in[16];
    const float* wc  = (const float*)d_in[17];
    const float* bc  = (const float*)d_in[18];
    float* out = (float*)d_out;

    cudaFuncSetAttribute(k_mlp,   cudaFuncAttributeMaxDynamicSharedMemorySize, SMEM_MLP_FLOATS * 4);
    cudaFuncSetAttribute(k_final, cudaFuncAttributeMaxDynamicSharedMemorySize, SMEM_FIN_FLOATS * 4);

    k_init<<<(NN * HH + 255) / 256, 256>>>();
    k_deg<<<(EE + 255) / 256, 256>>>(ei);
    k_dinv<<<(NN + 255) / 256, 256>>>();
    k_mlp<<<(NN + 63) / 64, 256, SMEM_MLP_FLOATS * 4>>>(x, w1, b1, w2, b2, w3, b3, wx, bx);
    {
        long long threads = (long long)MM * 16;
        int blocks = (int)((threads + 255) / 256);
        k_edge<<<blocks, 256>>>(ei, beta);
    }
    k_final<<<(NN + 63) / 64, 256, SMEM_FIN_FLOATS * 4>>>(wg1, bg1, wg2, bg2, wf, bf, wc, bc, out);
}

// round 3
// speedup vs baseline: 1.1449x; 1.1449x over previous
#include <cuda_runtime.h>

#define NN 100000
#define EE 1600000
#define HH 64
#define NB_SCAN 98   // ceil(100000/1024)

// ---------------- scratch (__device__ globals: allocation-free) ----------------
__device__ float4 g_h4[NN * 16];     // h  [N,64]
__device__ float4 g_agg4[NN * 16];   // GCN shared aggregation (written once, no atomics)
__device__ float4 g_acc4[NN * 16];   // AGNN output (already divided by softmax denom)
__device__ float  g_xproj[NN * HH];  // tanh(h@wx+bx)
__device__ float2 g_di[NN];          // .x = dinv = rsqrt(deg), .y = 1/(||h||+eps)
__device__ int    g_cnt[NN];         // in-edge count (no self loop)
__device__ int    g_incl[NN];        // block-local inclusive scan
__device__ int    g_bsum[128];
__device__ int    g_boff[128];
__device__ int    g_start[NN];
__device__ int    g_cursor[NN];
__device__ int    g_csr[EE];         // source node per in-edge, grouped by dest

// ---------------- CSR build ----------------
__global__ void k_zero_cnt() {
    int i = blockIdx.x * blockDim.x + threadIdx.x;
    if (i < NN) g_cnt[i] = 0;
}

__global__ void k_count(const int* __restrict__ ei) {
    int e = blockIdx.x * blockDim.x + threadIdx.x;
    if (e < EE) atomicAdd(&g_cnt[ei[EE + e]], 1);
}

__global__ void k_dinv() {
    int i = blockIdx.x * blockDim.x + threadIdx.x;
    if (i < NN) g_di[i].x = rsqrtf((float)(g_cnt[i] + 1));   // +1 self loop
}

__global__ void __launch_bounds__(1024) k_scan1() {
    int tid = threadIdx.x;
    int i = blockIdx.x * 1024 + tid;
    int v = (i < NN) ? g_cnt[i] : 0;
    int x = v;
#pragma unroll
    for (int d = 1; d < 32; d <<= 1) {
        int y = __shfl_up_sync(0xFFFFFFFFu, x, d);
        if ((tid & 31) >= d) x += y;
    }
    __shared__ int ws[32];
    if ((tid & 31) == 31) ws[tid >> 5] = x;
    __syncthreads();
    if (tid < 32) {
        int y = ws[tid];
#pragma unroll
        for (int d = 1; d < 32; d <<= 1) {
            int z = __shfl_up_sync(0xFFFFFFFFu, y, d);
            if (tid >= d) y += z;
        }
        ws[tid] = y;
    }
    __syncthreads();
    int incl = x + ((tid >= 32) ? ws[(tid >> 5) - 1] : 0);
    if (i < NN) g_incl[i] = incl;
    if (tid == 1023) g_bsum[blockIdx.x] = incl;
}

__global__ void k_scan2() {
    int tid = threadIdx.x;   // 128 threads
    int v = (tid < NB_SCAN) ? g_bsum[tid] : 0;
    int x = v;
#pragma unroll
    for (int d = 1; d < 32; d <<= 1) {
        int y = __shfl_up_sync(0xFFFFFFFFu, x, d);
        if ((tid & 31) >= d) x += y;
    }
    __shared__ int ws[4];
    if ((tid & 31) == 31) ws[tid >> 5] = x;
    __syncthreads();
    int add = 0;
    for (int w = 0; w < (tid >> 5); w++) add += ws[w];
    int incl = x + add;
    if (tid < NB_SCAN) g_boff[tid] = incl - v;   // exclusive
}

__global__ void __launch_bounds__(1024) k_scan3() {
    int i = blockIdx.x * 1024 + threadIdx.x;
    if (i < NN) {
        int st = g_incl[i] - g_cnt[i] + g_boff[blockIdx.x];
        g_start[i] = st;
        g_cursor[i] = st;
    }
}

__global__ void k_scatter(const int* __restrict__ ei) {
    int e = blockIdx.x * blockDim.x + threadIdx.x;
    if (e < EE) {
        int r = ei[e];
        int c = ei[EE + e];
        int p = atomicAdd(&g_cursor[c], 1);
        g_csr[p] = r;
    }
}

// ---------------- 64x64 tile GEMM helper (64 nodes/block, 256 thr, 4x4 blocking) ----
template <int ACT>
__device__ __forceinline__ void mm64(const float* __restrict__ inS,
                                     const float* __restrict__ wS,
                                     const float* __restrict__ bS,
                                     float* __restrict__ outS, int t) {
    const int jt = (t & 15) * 4;
    const int rt = (t >> 4) * 4;
    float acc[4][4];
#pragma unroll
    for (int i = 0; i < 4; i++)
#pragma unroll
        for (int q = 0; q < 4; q++) acc[i][q] = 0.f;
#pragma unroll 8
    for (int k = 0; k < 64; k++) {
        float4 wv = *reinterpret_cast<const float4*>(wS + (k << 6) + jt);
#pragma unroll
        for (int i = 0; i < 4; i++) {
            float xv = inS[(rt + i) * 65 + k];
            acc[i][0] = fmaf(xv, wv.x, acc[i][0]);
            acc[i][1] = fmaf(xv, wv.y, acc[i][1]);
            acc[i][2] = fmaf(xv, wv.z, acc[i][2]);
            acc[i][3] = fmaf(xv, wv.w, acc[i][3]);
        }
    }
#pragma unroll
    for (int i = 0; i < 4; i++)
#pragma unroll
        for (int q = 0; q < 4; q++) {
            float v = acc[i][q] + bS[jt + q];
            if (ACT == 1) v = fmaxf(v, 0.f);
            if (ACT == 2) v = tanhf(v);
            outS[(rt + i) * 65 + jt + q] = v;
        }
}

// ---------------- fused input MLP + xproj + inv-norm ----------------
#define SMEM_MLP_FLOATS 24960
__global__ void __launch_bounds__(256) k_mlp(
    const float* __restrict__ x,
    const float* __restrict__ w1, const float* __restrict__ b1,
    const float* __restrict__ w2, const float* __restrict__ b2,
    const float* __restrict__ w3, const float* __restrict__ b3,
    const float* __restrict__ wx, const float* __restrict__ bx) {
    extern __shared__ float sm[];
    float* w1s = sm;
    float* w2s = sm + 4096;
    float* w3s = sm + 8192;
    float* wxs = sm + 12288;
    float* bs  = sm + 16384;
    float* tA  = sm + 16640;
    float* tB  = sm + 20800;
    int t = threadIdx.x;
    for (int i = t; i < 4096; i += 256) {
        w1s[i] = w1[i]; w2s[i] = w2[i]; w3s[i] = w3[i]; wxs[i] = wx[i];
    }
    if (t < 64) { bs[t] = b1[t]; bs[64 + t] = b2[t]; bs[128 + t] = b3[t]; bs[192 + t] = bx[t]; }
    int n0 = blockIdx.x * 64;
    for (int i = t; i < 4096; i += 256) {
        int r = i >> 6, k = i & 63;
        int n = n0 + r;
        tA[r * 65 + k] = (n < NN) ? x[n * 64 + k] : 0.f;
    }
    __syncthreads();
    mm64<1>(tA, w1s, bs, tB, t);       __syncthreads();
    mm64<1>(tB, w2s, bs + 64, tA, t);  __syncthreads();
    mm64<0>(tA, w3s, bs + 128, tB, t); __syncthreads();   // h in tB
    float* gh = (float*)g_h4;
    for (int i = t; i < 4096; i += 256) {
        int r = i >> 6, k = i & 63;
        int n = n0 + r;
        if (n < NN) gh[n * 64 + k] = tB[r * 65 + k];
    }
    if (t < 64) {
        int n = n0 + t;
        if (n < NN) {
            float ss = 0.f;
#pragma unroll 8
            for (int k = 0; k < 64; k++) { float v = tB[t * 65 + k]; ss = fmaf(v, v, ss); }
            g_di[n].y = 1.f / (sqrtf(ss) + 1e-12f);
        }
    }
    __syncthreads();
    mm64<2>(tB, wxs, bs + 192, tA, t); __syncthreads();
    for (int i = t; i < 4096; i += 256) {
        int r = i >> 6, k = i & 63;
        int n = n0 + r;
        if (n < NN) g_xproj[n * 64 + k] = tA[r * 65 + k];
    }
}

// ---------------- CSR pull gather: one warp per node, 2 edges/warp-iter ----------
// agg[c] = dinv[c] * (dinv[c]*h[c] + sum_r dinv[r]*h[r])
// acc[c] = (sum e_r*h[r] + e_self*h[c]) / (sum e + e_self)
__global__ void __launch_bounds__(256) k_gather(const float* __restrict__ betap) {
    int warp = (blockIdx.x * 256 + threadIdx.x) >> 5;
    if (warp >= NN) return;
    int c = warp;
    int lane = threadIdx.x & 31;
    int sub = lane >> 4;
    int sl  = lane & 15;
    float beta = *betap;
    float4 hc = g_h4[c * 16 + sl];
    float2 dic = g_di[c];

    // self-loop
    float dps = hc.x * hc.x + hc.y * hc.y + hc.z * hc.z + hc.w * hc.w;
    dps += __shfl_xor_sync(0xFFFFFFFFu, dps, 1);
    dps += __shfl_xor_sync(0xFFFFFFFFu, dps, 2);
    dps += __shfl_xor_sync(0xFFFFFFFFu, dps, 4);
    dps += __shfl_xor_sync(0xFFFFFFFFu, dps, 8);
    float evs = __expf(beta * dps * dic.y * dic.y);
    float4 agg, acc;
    float s;
    if (sub == 0) {
        agg = make_float4(dic.x * hc.x, dic.x * hc.y, dic.x * hc.z, dic.x * hc.w);
        acc = make_float4(evs * hc.x, evs * hc.y, evs * hc.z, evs * hc.w);
        s = evs;
    } else {
        agg = make_float4(0.f, 0.f, 0.f, 0.f);
        acc = make_float4(0.f, 0.f, 0.f, 0.f);
        s = 0.f;
    }

    int beg = g_start[c];
    int cnt = g_cnt[c];
    int T = (cnt + 1) >> 1;
    // software pipeline: preload edge 0
    bool v0 = (sub < cnt);
    int r0 = v0 ? g_csr[beg + sub] : c;
    float4 h0 = g_h4[r0 * 16 + sl];
    float2 d0 = g_di[r0];
    for (int t = 0; t < T; t++) {
        int nx = 2 * (t + 1) + sub;
        bool vn = (nx < cnt);
        int rn = vn ? g_csr[beg + nx] : c;
        float4 hn = g_h4[rn * 16 + sl];
        float2 dn = g_di[rn];

        float dp = h0.x * hc.x + h0.y * hc.y + h0.z * hc.z + h0.w * hc.w;
        dp += __shfl_xor_sync(0xFFFFFFFFu, dp, 1);
        dp += __shfl_xor_sync(0xFFFFFFFFu, dp, 2);
        dp += __shfl_xor_sync(0xFFFFFFFFu, dp, 4);
        dp += __shfl_xor_sync(0xFFFFFFFFu, dp, 8);
        float ev = v0 ? __expf(beta * dp * d0.y * dic.y) : 0.f;
        float w  = v0 ? d0.x : 0.f;
        agg.x = fmaf(w, h0.x, agg.x);  agg.y = fmaf(w, h0.y, agg.y);
        agg.z = fmaf(w, h0.z, agg.z);  agg.w = fmaf(w, h0.w, agg.w);
        acc.x = fmaf(ev, h0.x, acc.x); acc.y = fmaf(ev, h0.y, acc.y);
        acc.z = fmaf(ev, h0.z, acc.z); acc.w = fmaf(ev, h0.w, acc.w);
        s += ev;

        v0 = vn; r0 = rn; h0 = hn; d0 = dn;
    }
    // combine halves (lane <-> lane^16)
    agg.x += __shfl_xor_sync(0xFFFFFFFFu, agg.x, 16);
    agg.y += __shfl_xor_sync(0xFFFFFFFFu, agg.y, 16);
    agg.z += __shfl_xor_sync(0xFFFFFFFFu, agg.z, 16);
    agg.w += __shfl_xor_sync(0xFFFFFFFFu, agg.w, 16);
    acc.x += __shfl_xor_sync(0xFFFFFFFFu, acc.x, 16);
    acc.y += __shfl_xor_sync(0xFFFFFFFFu, acc.y, 16);
    acc.z += __shfl_xor_sync(0xFFFFFFFFu, acc.z, 16);
    acc.w += __shfl_xor_sync(0xFFFFFFFFu, acc.w, 16);
    s     += __shfl_xor_sync(0xFFFFFFFFu, s, 16);
    if (sub == 0) {
        float invs = 1.f / s;
        g_agg4[c * 16 + sl] = make_float4(dic.x * agg.x, dic.x * agg.y,
                                          dic.x * agg.z, dic.x * agg.w);
        g_acc4[c * 16 + sl] = make_float4(invs * acc.x, invs * acc.y,
                                          invs * acc.z, invs * acc.w);
    }
}

// ---------------- fused filters + attention fusion + classifier ----------------
#define SMEM_FIN_FLOATS 31684
__global__ void __launch_bounds__(256) k_final(
    const float* __restrict__ wg1, const float* __restrict__ bg1,
    const float* __restrict__ wg2, const float* __restrict__ bg2,
    const float* __restrict__ wf,  const float* __restrict__ bf,
    const float* __restrict__ wc,  const float* __restrict__ bc,
    float* __restrict__ out) {
    extern __shared__ float sm[];
    float* wg1s = sm;
    float* wg2s = sm + 4096;
    float* wfs  = sm + 8192;
    float* wcs  = sm + 12288;
    float* bg1s = sm + 12544;
    float* bg2s = sm + 12608;
    float* bfs  = sm + 12672;
    float* bcs  = sm + 12736;
    float* aggS = sm + 12740;
    float* xpS  = sm + 16900;
    float* f0S  = sm + 21060;
    float* f1S  = sm + 25220;
    float* red0 = sm + 29380;
    float* red1 = sm + 30468;
    float* sc0  = sm + 31556;
    float* sc1  = sm + 31620;
    int t = threadIdx.x;
    for (int i = t; i < 4096; i += 256) { wg1s[i] = wg1[i]; wg2s[i] = wg2[i]; wfs[i] = wf[i]; }
    if (t < 256) wcs[t] = wc[t];
    if (t < 64) { bg1s[t] = bg1[t]; bg2s[t] = bg2[t]; bfs[t] = bf[t]; }
    if (t < 2) bcs[t] = bc[t];
    int n0 = blockIdx.x * 64;
    const float* agg = (const float*)g_agg4;
    for (int i = t; i < 4096; i += 256) {
        int r = i >> 6, k = i & 63;
        int n = n0 + r;
        aggS[r * 65 + k] = (n < NN) ? agg[n * 64 + k] : 0.f;
        xpS[r * 65 + k]  = (n < NN) ? g_xproj[n * 64 + k] : 0.f;
    }
    __syncthreads();
    const int jt = (t & 15) * 4;
    const int rt = (t >> 4) * 4;
    float f0r[4][4], f1r[4][4];
    {
        float a0[4][4] = {}, a1[4][4] = {};
#pragma unroll 4
        for (int k = 0; k < 64; k++) {
            float4 w1v = *(const float4*)(wg1s + (k << 6) + jt);
            float4 w2v = *(const float4*)(wg2s + (k << 6) + jt);
#pragma unroll
            for (int i = 0; i < 4; i++) {
                float xv = aggS[(rt + i) * 65 + k];
                a0[i][0] = fmaf(xv, w1v.x, a0[i][0]);
                a0[i][1] = fmaf(xv, w1v.y, a0[i][1]);
                a0[i][2] = fmaf(xv, w1v.z, a0[i][2]);
                a0[i][3] = fmaf(xv, w1v.w, a0[i][3]);
                a1[i][0] = fmaf(xv, w2v.x, a1[i][0]);
                a1[i][1] = fmaf(xv, w2v.y, a1[i][1]);
                a1[i][2] = fmaf(xv, w2v.z, a1[i][2]);
                a1[i][3] = fmaf(xv, w2v.w, a1[i][3]);
            }
        }
#pragma unroll
        for (int i = 0; i < 4; i++)
#pragma unroll
            for (int q = 0; q < 4; q++) {
                f0r[i][q] = a0[i][q] + bg1s[jt + q];
                f1r[i][q] = a1[i][q] + bg2s[jt + q];
                f0S[(rt + i) * 65 + jt + q] = f0r[i][q];
                f1S[(rt + i) * 65 + jt + q] = f1r[i][q];
            }
    }
    __syncthreads();
    float p0[4] = {0, 0, 0, 0}, p1[4] = {0, 0, 0, 0};
    {
        float a0[4][4] = {}, a1[4][4] = {};
#pragma unroll 4
        for (int k = 0; k < 64; k++) {
            float4 wv = *(const float4*)(wfs + (k << 6) + jt);
#pragma unroll
            for (int i = 0; i < 4; i++) {
                float x0 = f0S[(rt + i) * 65 + k];
                float x1 = f1S[(rt + i) * 65 + k];
                a0[i][0] = fmaf(x0, wv.x, a0[i][0]);
                a0[i][1] = fmaf(x0, wv.y, a0[i][1]);
                a0[i][2] = fmaf(x0, wv.z, a0[i][2]);
                a0[i][3] = fmaf(x0, wv.w, a0[i][3]);
                a1[i][0] = fmaf(x1, wv.x, a1[i][0]);
                a1[i][1] = fmaf(x1, wv.y, a1[i][1]);
                a1[i][2] = fmaf(x1, wv.z, a1[i][2]);
                a1[i][3] = fmaf(x1, wv.w, a1[i][3]);
            }
        }
#pragma unroll
        for (int i = 0; i < 4; i++)
#pragma unroll
            for (int q = 0; q < 4; q++) {
                float hp0 = tanhf(a0[i][q] + bfs[jt + q]);
                float hp1 = tanhf(a1[i][q] + bfs[jt + q]);
                float xp = xpS[(rt + i) * 65 + jt + q];
                p0[i] = fmaf(hp0, xp, p0[i]);
                p1[i] = fmaf(hp1, xp, p1[i]);
            }
    }
#pragma unroll
    for (int i = 0; i < 4; i++) {
        red0[(rt + i) * 17 + (t & 15)] = p0[i];
        red1[(rt + i) * 17 + (t & 15)] = p1[i];
    }
    __syncthreads();
    if (t < 64) {
        float l0 = 0.f, l1 = 0.f;
#pragma unroll
        for (int m = 0; m < 16; m++) { l0 += red0[t * 17 + m]; l1 += red1[t * 17 + m]; }
        float mx = fmaxf(l0, l1);
        float e0 = expf(l0 - mx), e1 = expf(l1 - mx);
        float inv = 1.f / (e0 + e1);
        sc0[t] = e0 * inv;
        sc1[t] = e1 * inv;
    }
    __syncthreads();
    const float* acc1 = (const float*)g_acc4;
#pragma unroll
    for (int i = 0; i < 4; i++) {
        int rr = rt + i;
        int n = n0 + rr;
        float y0 = 0.f, y1 = 0.f;
        if (n < NN) {
            float s0 = sc0[rr], s1 = sc1[rr];
            float4 hv = *(const float4*)(acc1 + n * 64 + jt);   // already normalized
            float h1v[4] = {hv.x, hv.y, hv.z, hv.w};
#pragma unroll
            for (int q = 0; q < 4; q++) {
                float res = s0 * f0r[i][q] + s1 * f1r[i][q];
                int j = jt + q;
                y0 += res * wcs[j * 2 + 0] + h1v[q] * wcs[(64 + j) * 2 + 0];
                y1 += res * wcs[j * 2 + 1] + h1v[q] * wcs[(64 + j) * 2 + 1];
            }
        }
        red0[rr * 17 + (t & 15)] = y0;
        red1[rr * 17 + (t & 15)] = y1;
    }
    __syncthreads();
    if (t < 64) {
        int n = n0 + t;
        if (n < NN) {
            float y0 = bcs[0], y1 = bcs[1];
#pragma unroll
            for (int m = 0; m < 16; m++) { y0 += red0[t * 17 + m]; y1 += red1[t * 17 + m]; }
            out[n * 2 + 0] = y0;
            out[n * 2 + 1] = y1;
        }
    }
}

// ---------------- launch ----------------
extern "C" void kernel_launch(void* const* d_in, const int* in_sizes, int n_in,
                              void* d_out, int out_size) {
    const float* x   = (const float*)d_in[0];
    const int*   ei  = (const int*)d_in[1];      // int32 (JAX default)
    const float* w1  = (const float*)d_in[2];
    const float* b1  = (const float*)d_in[3];
    const float* w2  = (const float*)d_in[4];
    const float* b2  = (const float*)d_in[5];
    const float* w3  = (const float*)d_in[6];
    const float* b3  = (const float*)d_in[7];
    const float* wg1 = (const float*)d_in[8];
    const float* bg1 = (const float*)d_in[9];
    const float* wg2 = (const float*)d_in[10];
    const float* bg2 = (const float*)d_in[11];
    const float* beta= (const float*)d_in[12];
    const float* wf  = (const float*)d_in[13];
    const float* bf  = (const float*)d_in[14];
    const float* wx  = (const float*)d_in[15];
    const float* bx  = (const float*)d_in[16];
    const float* wc  = (const float*)d_in[17];
    const float* bc  = (const float*)d_in[18];
    float* out = (float*)d_out;

    cudaFuncSetAttribute(k_mlp,   cudaFuncAttributeMaxDynamicSharedMemorySize, SMEM_MLP_FLOATS * 4);
    cudaFuncSetAttribute(k_final, cudaFuncAttributeMaxDynamicSharedMemorySize, SMEM_FIN_FLOATS * 4);

    // CSR build
    k_zero_cnt<<<(NN + 255) / 256, 256>>>();
    k_count<<<(EE + 255) / 256, 256>>>(ei);
    k_dinv<<<(NN + 255) / 256, 256>>>();
    k_scan1<<<NB_SCAN, 1024>>>();
    k_scan2<<<1, 128>>>();
    k_scan3<<<NB_SCAN, 1024>>>();
    k_scatter<<<(EE + 255) / 256, 256>>>(ei);
    // node features
    k_mlp<<<(NN + 63) / 64, 256, SMEM_MLP_FLOATS * 4>>>(x, w1, b1, w2, b2, w3, b3, wx, bx);
    // pull-mode edge aggregation (no atomics)
    k_gather<<<(NN * 32 + 255) / 256, 256>>>(beta);
    // epilogue
    k_final<<<(NN + 63) / 64, 256, SMEM_FIN_FLOATS * 4>>>(wg1, bg1, wg2, bg2, wf, bf, wc, bc, out);
}

// round 4
// speedup vs baseline: 1.7641x; 1.5408x over previous
#include <cuda_runtime.h>

#define NN 100000
#define EE 1600000
#define HH 64
#define NB_SCAN 98   // ceil(100000/1024)
#define TP 68        // tile pitch (floats): 272B = 17*16B, alignment-preserving

typedef unsigned long long ull;

// ---------------- f32x2 packed-FMA helpers ----------------
__device__ __forceinline__ ull pk2(float lo, float hi) {
    ull r; asm("mov.b64 %0,{%1,%2};" : "=l"(r) : "f"(lo), "f"(hi)); return r;
}
__device__ __forceinline__ void fma2(ull& d, ull a, ull b) {
    asm("fma.rn.f32x2 %0,%1,%2,%0;" : "+l"(d) : "l"(a), "l"(b));
}
__device__ __forceinline__ float2 upk(ull v) {
    float lo, hi; asm("mov.b64 {%0,%1},%2;" : "=f"(lo), "=f"(hi) : "l"(v));
    return make_float2(lo, hi);
}

// ---------------- scratch ----------------
__device__ float4 g_h4[NN * 16];     // h  [N,64]
__device__ float4 g_agg4[NN * 16];   // GCN shared aggregation
__device__ float4 g_acc4[NN * 16];   // AGNN output (normalized)
__device__ float4 g_xp4[NN * 16];    // tanh(h@wx+bx)
__device__ float2 g_di[NN];          // .x = rsqrt(deg), .y = 1/(||h||+eps)
__device__ int    g_cnt[NN];
__device__ int    g_incl[NN];
__device__ int    g_bsum[128];
__device__ int    g_boff[128];
__device__ int    g_start[NN];
__device__ int    g_cursor[NN];
__device__ int    g_csr[EE];

// ---------------- CSR build ----------------
__global__ void k_zero_cnt() {
    int i = blockIdx.x * blockDim.x + threadIdx.x;
    if (i < NN) g_cnt[i] = 0;
}
__global__ void k_count(const int* __restrict__ ei) {
    int e = blockIdx.x * blockDim.x + threadIdx.x;
    if (e < EE) atomicAdd(&g_cnt[ei[EE + e]], 1);
}
__global__ void k_dinv() {
    int i = blockIdx.x * blockDim.x + threadIdx.x;
    if (i < NN) g_di[i].x = rsqrtf((float)(g_cnt[i] + 1));
}
__global__ void __launch_bounds__(1024) k_scan1() {
    int tid = threadIdx.x;
    int i = blockIdx.x * 1024 + tid;
    int v = (i < NN) ? g_cnt[i] : 0;
    int x = v;
#pragma unroll
    for (int d = 1; d < 32; d <<= 1) {
        int y = __shfl_up_sync(0xFFFFFFFFu, x, d);
        if ((tid & 31) >= d) x += y;
    }
    __shared__ int ws[32];
    if ((tid & 31) == 31) ws[tid >> 5] = x;
    __syncthreads();
    if (tid < 32) {
        int y = ws[tid];
#pragma unroll
        for (int d = 1; d < 32; d <<= 1) {
            int z = __shfl_up_sync(0xFFFFFFFFu, y, d);
            if (tid >= d) y += z;
        }
        ws[tid] = y;
    }
    __syncthreads();
    int incl = x + ((tid >= 32) ? ws[(tid >> 5) - 1] : 0);
    if (i < NN) g_incl[i] = incl;
    if (tid == 1023) g_bsum[blockIdx.x] = incl;
}
__global__ void k_scan2() {
    int tid = threadIdx.x;   // 128
    int v = (tid < NB_SCAN) ? g_bsum[tid] : 0;
    int x = v;
#pragma unroll
    for (int d = 1; d < 32; d <<= 1) {
        int y = __shfl_up_sync(0xFFFFFFFFu, x, d);
        if ((tid & 31) >= d) x += y;
    }
    __shared__ int ws[4];
    if ((tid & 31) == 31) ws[tid >> 5] = x;
    __syncthreads();
    int add = 0;
    for (int w = 0; w < (tid >> 5); w++) add += ws[w];
    if (tid < NB_SCAN) g_boff[tid] = x + add - v;
}
__global__ void __launch_bounds__(1024) k_scan3() {
    int i = blockIdx.x * 1024 + threadIdx.x;
    if (i < NN) {
        int st = g_incl[i] - g_cnt[i] + g_boff[blockIdx.x];
        g_start[i] = st;
        g_cursor[i] = st;
    }
}
__global__ void k_scatter(const int* __restrict__ ei) {
    int e = blockIdx.x * blockDim.x + threadIdx.x;
    if (e < EE) {
        int r = ei[e];
        int c = ei[EE + e];
        g_csr[atomicAdd(&g_cursor[c], 1)] = r;
    }
}

// ---------------- packed 64x64 GEMM core: acc[i][p] = rows rt+i, col-pairs (jt+2p, jt+2p+1)
__device__ __forceinline__ void gemm_core(const float* __restrict__ inS,
                                          const float* __restrict__ wS,
                                          int rt, int jt, ull acc[4][2]) {
#pragma unroll
    for (int i = 0; i < 4; i++) { acc[i][0] = 0ull; acc[i][1] = 0ull; }
#pragma unroll 4
    for (int k0 = 0; k0 < 64; k0 += 4) {
        float4 xv0 = *(const float4*)(inS + (rt + 0) * TP + k0);
        float4 xv1 = *(const float4*)(inS + (rt + 1) * TP + k0);
        float4 xv2 = *(const float4*)(inS + (rt + 2) * TP + k0);
        float4 xv3 = *(const float4*)(inS + (rt + 3) * TP + k0);
#pragma unroll
        for (int kk = 0; kk < 4; kk++) {
            float4 wv = *(const float4*)(wS + ((k0 + kk) << 6) + jt);
            ull w0 = pk2(wv.x, wv.y), w1 = pk2(wv.z, wv.w);
            float x0 = kk == 0 ? xv0.x : kk == 1 ? xv0.y : kk == 2 ? xv0.z : xv0.w;
            float x1 = kk == 0 ? xv1.x : kk == 1 ? xv1.y : kk == 2 ? xv1.z : xv1.w;
            float x2 = kk == 0 ? xv2.x : kk == 1 ? xv2.y : kk == 2 ? xv2.z : xv2.w;
            float x3 = kk == 0 ? xv3.x : kk == 1 ? xv3.y : kk == 2 ? xv3.z : xv3.w;
            ull p;
            p = pk2(x0, x0); fma2(acc[0][0], p, w0); fma2(acc[0][1], p, w1);
            p = pk2(x1, x1); fma2(acc[1][0], p, w0); fma2(acc[1][1], p, w1);
            p = pk2(x2, x2); fma2(acc[2][0], p, w0); fma2(acc[2][1], p, w1);
            p = pk2(x3, x3); fma2(acc[3][0], p, w0); fma2(acc[3][1], p, w1);
        }
    }
}

// dual-input version (shared weights)
__device__ __forceinline__ void gemm_core2(const float* __restrict__ in0,
                                           const float* __restrict__ in1,
                                           const float* __restrict__ wS,
                                           int rt, int jt, ull a0[4][2], ull a1[4][2]) {
#pragma unroll
    for (int i = 0; i < 4; i++) { a0[i][0] = a0[i][1] = 0ull; a1[i][0] = a1[i][1] = 0ull; }
#pragma unroll 2
    for (int k0 = 0; k0 < 64; k0 += 4) {
        float4 u0 = *(const float4*)(in0 + (rt + 0) * TP + k0);
        float4 u1 = *(const float4*)(in0 + (rt + 1) * TP + k0);
        float4 u2 = *(const float4*)(in0 + (rt + 2) * TP + k0);
        float4 u3 = *(const float4*)(in0 + (rt + 3) * TP + k0);
        float4 v0 = *(const float4*)(in1 + (rt + 0) * TP + k0);
        float4 v1 = *(const float4*)(in1 + (rt + 1) * TP + k0);
        float4 v2 = *(const float4*)(in1 + (rt + 2) * TP + k0);
        float4 v3 = *(const float4*)(in1 + (rt + 3) * TP + k0);
#pragma unroll
        for (int kk = 0; kk < 4; kk++) {
            float4 wv = *(const float4*)(wS + ((k0 + kk) << 6) + jt);
            ull w0 = pk2(wv.x, wv.y), w1 = pk2(wv.z, wv.w);
            float s0 = kk == 0 ? u0.x : kk == 1 ? u0.y : kk == 2 ? u0.z : u0.w;
            float s1 = kk == 0 ? u1.x : kk == 1 ? u1.y : kk == 2 ? u1.z : u1.w;
            float s2 = kk == 0 ? u2.x : kk == 1 ? u2.y : kk == 2 ? u2.z : u2.w;
            float s3 = kk == 0 ? u3.x : kk == 1 ? u3.y : kk == 2 ? u3.z : u3.w;
            float t0 = kk == 0 ? v0.x : kk == 1 ? v0.y : kk == 2 ? v0.z : v0.w;
            float t1 = kk == 0 ? v1.x : kk == 1 ? v1.y : kk == 2 ? v1.z : v1.w;
            float t2 = kk == 0 ? v2.x : kk == 1 ? v2.y : kk == 2 ? v2.z : v2.w;
            float t3 = kk == 0 ? v3.x : kk == 1 ? v3.y : kk == 2 ? v3.z : v3.w;
            ull p;
            p = pk2(s0, s0); fma2(a0[0][0], p, w0); fma2(a0[0][1], p, w1);
            p = pk2(s1, s1); fma2(a0[1][0], p, w0); fma2(a0[1][1], p, w1);
            p = pk2(s2, s2); fma2(a0[2][0], p, w0); fma2(a0[2][1], p, w1);
            p = pk2(s3, s3); fma2(a0[3][0], p, w0); fma2(a0[3][1], p, w1);
            p = pk2(t0, t0); fma2(a1[0][0], p, w0); fma2(a1[0][1], p, w1);
            p = pk2(t1, t1); fma2(a1[1][0], p, w0); fma2(a1[1][1], p, w1);
            p = pk2(t2, t2); fma2(a1[2][0], p, w0); fma2(a1[2][1], p, w1);
            p = pk2(t3, t3); fma2(a1[3][0], p, w0); fma2(a1[3][1], p, w1);
        }
    }
}

// ---------------- fused input MLP + xproj + inv-norm ----------------
// smem floats: ws 4096 | bs 256 | tA 4352 | tB 4352  = 13056 (52.2 KB)
#define SMEM_MLP_FLOATS 13056
__global__ void __launch_bounds__(256) k_mlp(
    const float* __restrict__ x,
    const float* __restrict__ w1, const float* __restrict__ b1,
    const float* __restrict__ w2, const float* __restrict__ b2,
    const float* __restrict__ w3, const float* __restrict__ b3,
    const float* __restrict__ wx, const float* __restrict__ bx) {
    extern __shared__ float sm[];
    float* ws = sm;
    float* bs = sm + 4096;
    float* tA = sm + 4352;
    float* tB = sm + 8704;
    int t = threadIdx.x;
    const int jt = (t & 15) * 4;
    const int rt = (t >> 4) * 4;
    int n0 = blockIdx.x * 64;

    if (t < 64) { bs[t] = b1[t]; bs[64 + t] = b2[t]; bs[128 + t] = b3[t]; bs[192 + t] = bx[t]; }
    for (int i = t; i < 1024; i += 256) {
        int r = i >> 4, s4 = i & 15;
        int n = n0 + r;
        float4 v = (n < NN) ? *(const float4*)(x + n * 64 + s4 * 4) : make_float4(0, 0, 0, 0);
        *(float4*)(tA + r * TP + s4 * 4) = v;
        ((float4*)ws)[i] = ((const float4*)w1)[i];
    }
    __syncthreads();

    ull acc[4][2];
    // L1: tA -> tB (relu)
    gemm_core(tA, ws, rt, jt, acc);
    __syncthreads();
#pragma unroll
    for (int i = 0; i < 4; i++) {
        float2 p0 = upk(acc[i][0]), p1 = upk(acc[i][1]);
        tB[(rt + i) * TP + jt + 0] = fmaxf(p0.x + bs[jt + 0], 0.f);
        tB[(rt + i) * TP + jt + 1] = fmaxf(p0.y + bs[jt + 1], 0.f);
        tB[(rt + i) * TP + jt + 2] = fmaxf(p1.x + bs[jt + 2], 0.f);
        tB[(rt + i) * TP + jt + 3] = fmaxf(p1.y + bs[jt + 3], 0.f);
    }
    for (int i = t; i < 1024; i += 256) ((float4*)ws)[i] = ((const float4*)w2)[i];
    __syncthreads();
    // L2: tB -> tA (relu)
    gemm_core(tB, ws, rt, jt, acc);
    __syncthreads();
#pragma unroll
    for (int i = 0; i < 4; i++) {
        float2 p0 = upk(acc[i][0]), p1 = upk(acc[i][1]);
        tA[(rt + i) * TP + jt + 0] = fmaxf(p0.x + bs[64 + jt + 0], 0.f);
        tA[(rt + i) * TP + jt + 1] = fmaxf(p0.y + bs[64 + jt + 1], 0.f);
        tA[(rt + i) * TP + jt + 2] = fmaxf(p1.x + bs[64 + jt + 2], 0.f);
        tA[(rt + i) * TP + jt + 3] = fmaxf(p1.y + bs[64 + jt + 3], 0.f);
    }
    for (int i = t; i < 1024; i += 256) ((float4*)ws)[i] = ((const float4*)w3)[i];
    __syncthreads();
    // L3: tA -> tB (h, no act) + global h store
    gemm_core(tA, ws, rt, jt, acc);
    __syncthreads();
#pragma unroll
    for (int i = 0; i < 4; i++) {
        float2 p0 = upk(acc[i][0]), p1 = upk(acc[i][1]);
        float h0 = p0.x + bs[128 + jt + 0];
        float h1 = p0.y + bs[128 + jt + 1];
        float h2 = p1.x + bs[128 + jt + 2];
        float h3 = p1.y + bs[128 + jt + 3];
        tB[(rt + i) * TP + jt + 0] = h0;
        tB[(rt + i) * TP + jt + 1] = h1;
        tB[(rt + i) * TP + jt + 2] = h2;
        tB[(rt + i) * TP + jt + 3] = h3;
        int n = n0 + rt + i;
        if (n < NN) g_h4[n * 16 + (jt >> 2)] = make_float4(h0, h1, h2, h3);
    }
    for (int i = t; i < 1024; i += 256) ((float4*)ws)[i] = ((const float4*)wx)[i];
    __syncthreads();
    // inv-norm
    if (t < 64) {
        int n = n0 + t;
        if (n < NN) {
            float ss = 0.f;
#pragma unroll 8
            for (int k = 0; k < 64; k++) { float v = tB[t * TP + k]; ss = fmaf(v, v, ss); }
            g_di[n].y = 1.f / (sqrtf(ss) + 1e-12f);
        }
    }
    // L4: tB -> xproj (tanh), straight to global
    gemm_core(tB, ws, rt, jt, acc);
#pragma unroll
    for (int i = 0; i < 4; i++) {
        int n = n0 + rt + i;
        if (n < NN) {
            float2 p0 = upk(acc[i][0]), p1 = upk(acc[i][1]);
            g_xp4[n * 16 + (jt >> 2)] = make_float4(
                tanhf(p0.x + bs[192 + jt + 0]), tanhf(p0.y + bs[192 + jt + 1]),
                tanhf(p1.x + bs[192 + jt + 2]), tanhf(p1.y + bs[192 + jt + 3]));
        }
    }
}

// ---------------- CSR pull gather: warp/node, 8 lanes/edge, 4 edges/iter ----------
__global__ void __launch_bounds__(256) k_gather(const float* __restrict__ betap) {
    int warp = (blockIdx.x * 256 + threadIdx.x) >> 5;
    if (warp >= NN) return;
    int c = warp;
    int lane = threadIdx.x & 31;
    int sub = lane >> 3;
    int sl  = lane & 7;
    float beta = *betap;
    float4 hc0 = g_h4[c * 16 + sl * 2];
    float4 hc1 = g_h4[c * 16 + sl * 2 + 1];
    float2 dic = g_di[c];

    float dps = hc0.x * hc0.x + hc0.y * hc0.y + hc0.z * hc0.z + hc0.w * hc0.w
              + hc1.x * hc1.x + hc1.y * hc1.y + hc1.z * hc1.z + hc1.w * hc1.w;
    dps += __shfl_xor_sync(0xFFFFFFFFu, dps, 1);
    dps += __shfl_xor_sync(0xFFFFFFFFu, dps, 2);
    dps += __shfl_xor_sync(0xFFFFFFFFu, dps, 4);
    float evs = __expf(beta * dps * dic.y * dic.y);
    float4 agg0, agg1, acc0, acc1;
    float s;
    if (sub == 0) {
        agg0 = make_float4(dic.x * hc0.x, dic.x * hc0.y, dic.x * hc0.z, dic.x * hc0.w);
        agg1 = make_float4(dic.x * hc1.x, dic.x * hc1.y, dic.x * hc1.z, dic.x * hc1.w);
        acc0 = make_float4(evs * hc0.x, evs * hc0.y, evs * hc0.z, evs * hc0.w);
        acc1 = make_float4(evs * hc1.x, evs * hc1.y, evs * hc1.z, evs * hc1.w);
        s = evs;
    } else {
        agg0 = agg1 = acc0 = acc1 = make_float4(0.f, 0.f, 0.f, 0.f);
        s = 0.f;
    }

    int beg = g_start[c];
    int cnt = g_cnt[c];
    int T = (cnt + 3) >> 2;
    bool v0 = (sub < cnt);
    int r0 = v0 ? g_csr[beg + sub] : c;
    float4 a0 = g_h4[r0 * 16 + sl * 2];
    float4 b0 = g_h4[r0 * 16 + sl * 2 + 1];
    float2 d0 = g_di[r0];
    for (int it = 0; it < T; it++) {
        int nx = 4 * (it + 1) + sub;
        bool vn = (nx < cnt);
        int rn = vn ? g_csr[beg + nx] : c;
        float4 an = g_h4[rn * 16 + sl * 2];
        float4 bn = g_h4[rn * 16 + sl * 2 + 1];
        float2 dn = g_di[rn];

        float dp = a0.x * hc0.x + a0.y * hc0.y + a0.z * hc0.z + a0.w * hc0.w
                 + b0.x * hc1.x + b0.y * hc1.y + b0.z * hc1.z + b0.w * hc1.w;
        dp += __shfl_xor_sync(0xFFFFFFFFu, dp, 1);
        dp += __shfl_xor_sync(0xFFFFFFFFu, dp, 2);
        dp += __shfl_xor_sync(0xFFFFFFFFu, dp, 4);
        float ev = v0 ? __expf(beta * dp * d0.y * dic.y) : 0.f;
        float w  = v0 ? d0.x : 0.f;
        agg0.x = fmaf(w, a0.x, agg0.x); agg0.y = fmaf(w, a0.y, agg0.y);
        agg0.z = fmaf(w, a0.z, agg0.z); agg0.w = fmaf(w, a0.w, agg0.w);
        agg1.x = fmaf(w, b0.x, agg1.x); agg1.y = fmaf(w, b0.y, agg1.y);
        agg1.z = fmaf(w, b0.z, agg1.z); agg1.w = fmaf(w, b0.w, agg1.w);
        acc0.x = fmaf(ev, a0.x, acc0.x); acc0.y = fmaf(ev, a0.y, acc0.y);
        acc0.z = fmaf(ev, a0.z, acc0.z); acc0.w = fmaf(ev, a0.w, acc0.w);
        acc1.x = fmaf(ev, b0.x, acc1.x); acc1.y = fmaf(ev, b0.y, acc1.y);
        acc1.z = fmaf(ev, b0.z, acc1.z); acc1.w = fmaf(ev, b0.w, acc1.w);
        s += ev;
        v0 = vn; r0 = rn; a0 = an; b0 = bn; d0 = dn;
    }
    // combine the 4 sub-groups (xor 8, then xor 16)
#pragma unroll
    for (int d = 8; d <= 16; d <<= 1) {
        agg0.x += __shfl_xor_sync(0xFFFFFFFFu, agg0.x, d);
        agg0.y += __shfl_xor_sync(0xFFFFFFFFu, agg0.y, d);
        agg0.z += __shfl_xor_sync(0xFFFFFFFFu, agg0.z, d);
        agg0.w += __shfl_xor_sync(0xFFFFFFFFu, agg0.w, d);
        agg1.x += __shfl_xor_sync(0xFFFFFFFFu, agg1.x, d);
        agg1.y += __shfl_xor_sync(0xFFFFFFFFu, agg1.y, d);
        agg1.z += __shfl_xor_sync(0xFFFFFFFFu, agg1.z, d);
        agg1.w += __shfl_xor_sync(0xFFFFFFFFu, agg1.w, d);
        acc0.x += __shfl_xor_sync(0xFFFFFFFFu, acc0.x, d);
        acc0.y += __shfl_xor_sync(0xFFFFFFFFu, acc0.y, d);
        acc0.z += __shfl_xor_sync(0xFFFFFFFFu, acc0.z, d);
        acc0.w += __shfl_xor_sync(0xFFFFFFFFu, acc0.w, d);
        acc1.x += __shfl_xor_sync(0xFFFFFFFFu, acc1.x, d);
        acc1.y += __shfl_xor_sync(0xFFFFFFFFu, acc1.y, d);
        acc1.z += __shfl_xor_sync(0xFFFFFFFFu, acc1.z, d);
        acc1.w += __shfl_xor_sync(0xFFFFFFFFu, acc1.w, d);
        s += __shfl_xor_sync(0xFFFFFFFFu, s, d);
    }
    if (sub == 0) {
        float invs = 1.f / s;
        g_agg4[c * 16 + sl * 2] = make_float4(dic.x * agg0.x, dic.x * agg0.y, dic.x * agg0.z, dic.x * agg0.w);
        g_agg4[c * 16 + sl * 2 + 1] = make_float4(dic.x * agg1.x, dic.x * agg1.y, dic.x * agg1.z, dic.x * agg1.w);
        g_acc4[c * 16 + sl * 2] = make_float4(invs * acc0.x, invs * acc0.y, invs * acc0.z, invs * acc0.w);
        g_acc4[c * 16 + sl * 2 + 1] = make_float4(invs * acc1.x, invs * acc1.y, invs * acc1.z, invs * acc1.w);
    }
}

// ---------------- fused filters + attention fusion + classifier ----------------
// smem floats: ws 4096 | wcs 256 | bs 200 | aggS 4352 | f0S 4352 | f1S 4352 |
//              red0 1088 | red1 1088 | sc0 64 | sc1 64  = 19912 (79.6 KB)
#define SMEM_FIN_FLOATS 19912
__global__ void __launch_bounds__(256) k_final(
    const float* __restrict__ wg1, const float* __restrict__ bg1,
    const float* __restrict__ wg2, const float* __restrict__ bg2,
    const float* __restrict__ wf,  const float* __restrict__ bf,
    const float* __restrict__ wc,  const float* __restrict__ bc,
    float* __restrict__ out) {
    extern __shared__ float sm[];
    float* ws   = sm;
    float* wcs  = sm + 4096;
    float* bs   = sm + 4352;   // bg1|bg2|bf|bc(2)  (200)
    float* aggS = sm + 4552;
    float* f0S  = sm + 8904;
    float* f1S  = sm + 13256;
    float* red0 = sm + 17608;
    float* red1 = sm + 18696;
    float* sc0  = sm + 19784;
    float* sc1  = sm + 19848;
    int t = threadIdx.x;
    const int jt = (t & 15) * 4;
    const int rt = (t >> 4) * 4;
    int n0 = blockIdx.x * 64;

    if (t < 256) wcs[t] = wc[t];
    if (t < 64) { bs[t] = bg1[t]; bs[64 + t] = bg2[t]; bs[128 + t] = bf[t]; }
    if (t < 2) bs[192 + t] = bc[t];
    const float* agg = (const float*)g_agg4;
    for (int i = t; i < 1024; i += 256) {
        int r = i >> 4, s4 = i & 15;
        int n = n0 + r;
        float4 v = (n < NN) ? *(const float4*)(agg + n * 64 + s4 * 4) : make_float4(0, 0, 0, 0);
        *(float4*)(aggS + r * TP + s4 * 4) = v;
        ((float4*)ws)[i] = ((const float4*)wg1)[i];
    }
    __syncthreads();

    ull acc[4][2];
    float2 f0r[4][2], f1r[4][2];
    // f0 = aggS @ wg1 + bg1
    gemm_core(aggS, ws, rt, jt, acc);
    __syncthreads();
#pragma unroll
    for (int i = 0; i < 4; i++) {
        float2 p0 = upk(acc[i][0]), p1 = upk(acc[i][1]);
        f0r[i][0] = make_float2(p0.x + bs[jt + 0], p0.y + bs[jt + 1]);
        f0r[i][1] = make_float2(p1.x + bs[jt + 2], p1.y + bs[jt + 3]);
        f0S[(rt + i) * TP + jt + 0] = f0r[i][0].x;
        f0S[(rt + i) * TP + jt + 1] = f0r[i][0].y;
        f0S[(rt + i) * TP + jt + 2] = f0r[i][1].x;
        f0S[(rt + i) * TP + jt + 3] = f0r[i][1].y;
    }
    for (int i = t; i < 1024; i += 256) ((float4*)ws)[i] = ((const float4*)wg2)[i];
    __syncthreads();
    // f1 = aggS @ wg2 + bg2
    gemm_core(aggS, ws, rt, jt, acc);
    __syncthreads();
#pragma unroll
    for (int i = 0; i < 4; i++) {
        float2 p0 = upk(acc[i][0]), p1 = upk(acc[i][1]);
        f1r[i][0] = make_float2(p0.x + bs[64 + jt + 0], p0.y + bs[64 + jt + 1]);
        f1r[i][1] = make_float2(p1.x + bs[64 + jt + 2], p1.y + bs[64 + jt + 3]);
        f1S[(rt + i) * TP + jt + 0] = f1r[i][0].x;
        f1S[(rt + i) * TP + jt + 1] = f1r[i][0].y;
        f1S[(rt + i) * TP + jt + 2] = f1r[i][1].x;
        f1S[(rt + i) * TP + jt + 3] = f1r[i][1].y;
    }
    for (int i = t; i < 1024; i += 256) ((float4*)ws)[i] = ((const float4*)wf)[i];
    __syncthreads();
    // hp_k = tanh(f_k @ wf + bf); logits partial = hp_k . xproj
    ull a0[4][2], a1[4][2];
    gemm_core2(f0S, f1S, ws, rt, jt, a0, a1);
    float p0a[4], p1a[4];
    const float* xp = (const float*)g_xp4;
#pragma unroll
    for (int i = 0; i < 4; i++) {
        int n = n0 + rt + i;
        float4 xv = (n < NN) ? *(const float4*)(xp + n * 64 + jt) : make_float4(0, 0, 0, 0);
        float2 q0 = upk(a0[i][0]), q1 = upk(a0[i][1]);
        float2 r0 = upk(a1[i][0]), r1 = upk(a1[i][1]);
        float h00 = tanhf(q0.x + bs[128 + jt + 0]);
        float h01 = tanhf(q0.y + bs[128 + jt + 1]);
        float h02 = tanhf(q1.x + bs[128 + jt + 2]);
        float h03 = tanhf(q1.y + bs[128 + jt + 3]);
        float h10 = tanhf(r0.x + bs[128 + jt + 0]);
        float h11 = tanhf(r0.y + bs[128 + jt + 1]);
        float h12 = tanhf(r1.x + bs[128 + jt + 2]);
        float h13 = tanhf(r1.y + bs[128 + jt + 3]);
        p0a[i] = h00 * xv.x + h01 * xv.y + h02 * xv.z + h03 * xv.w;
        p1a[i] = h10 * xv.x + h11 * xv.y + h12 * xv.z + h13 * xv.w;
    }
#pragma unroll
    for (int i = 0; i < 4; i++) {
        red0[(rt + i) * 17 + (t & 15)] = p0a[i];
        red1[(rt + i) * 17 + (t & 15)] = p1a[i];
    }
    __syncthreads();
    if (t < 64) {
        float l0 = 0.f, l1 = 0.f;
#pragma unroll
        for (int m = 0; m < 16; m++) { l0 += red0[t * 17 + m]; l1 += red1[t * 17 + m]; }
        float mx = fmaxf(l0, l1);
        float e0 = expf(l0 - mx), e1 = expf(l1 - mx);
        float inv = 1.f / (e0 + e1);
        sc0[t] = e0 * inv;
        sc1[t] = e1 * inv;
    }
    __syncthreads();
    const float* acc1g = (const float*)g_acc4;
#pragma unroll
    for (int i = 0; i < 4; i++) {
        int rr = rt + i;
        int n = n0 + rr;
        float y0 = 0.f, y1 = 0.f;
        if (n < NN) {
            float s0 = sc0[rr], s1 = sc1[rr];
            float4 hv = *(const float4*)(acc1g + n * 64 + jt);
            float fr[4] = {
                s0 * f0r[i][0].x + s1 * f1r[i][0].x,
                s0 * f0r[i][0].y + s1 * f1r[i][0].y,
                s0 * f0r[i][1].x + s1 * f1r[i][1].x,
                s0 * f0r[i][1].y + s1 * f1r[i][1].y };
            float h1v[4] = {hv.x, hv.y, hv.z, hv.w};
#pragma unroll
            for (int q = 0; q < 4; q++) {
                int j = jt + q;
                y0 += fr[q] * wcs[j * 2 + 0] + h1v[q] * wcs[(64 + j) * 2 + 0];
                y1 += fr[q] * wcs[j * 2 + 1] + h1v[q] * wcs[(64 + j) * 2 + 1];
            }
        }
        red0[rr * 17 + (t & 15)] = y0;
        red1[rr * 17 + (t & 15)] = y1;
    }
    __syncthreads();
    if (t < 64) {
        int n = n0 + t;
        if (n < NN) {
            float y0 = bs[192], y1 = bs[193];
#pragma unroll
            for (int m = 0; m < 16; m++) { y0 += red0[t * 17 + m]; y1 += red1[t * 17 + m]; }
            out[n * 2 + 0] = y0;
            out[n * 2 + 1] = y1;
        }
    }
}

// ---------------- launch ----------------
extern "C" void kernel_launch(void* const* d_in, const int* in_sizes, int n_in,
                              void* d_out, int out_size) {
    const float* x   = (const float*)d_in[0];
    const int*   ei  = (const int*)d_in[1];
    const float* w1  = (const float*)d_in[2];
    const float* b1  = (const float*)d_in[3];
    const float* w2  = (const float*)d_in[4];
    const float* b2  = (const float*)d_in[5];
    const float* w3  = (const float*)d_in[6];
    const float* b3  = (const float*)d_in[7];
    const float* wg1 = (const float*)d_in[8];
    const float* bg1 = (const float*)d_in[9];
    const float* wg2 = (const float*)d_in[10];
    const float* bg2 = (const float*)d_in[11];
    const float* beta= (const float*)d_in[12];
    const float* wf  = (const float*)d_in[13];
    const float* bf  = (const float*)d_in[14];
    const float* wx  = (const float*)d_in[15];
    const float* bx  = (const float*)d_in[16];
    const float* wc  = (const float*)d_in[17];
    const float* bc  = (const float*)d_in[18];
    float* out = (float*)d_out;

    cudaFuncSetAttribute(k_mlp,   cudaFuncAttributeMaxDynamicSharedMemorySize, SMEM_MLP_FLOATS * 4);
    cudaFuncSetAttribute(k_final, cudaFuncAttributeMaxDynamicSharedMemorySize, SMEM_FIN_FLOATS * 4);

    k_zero_cnt<<<(NN + 255) / 256, 256>>>();
    k_count<<<(EE + 255) / 256, 256>>>(ei);
    k_dinv<<<(NN + 255) / 256, 256>>>();
    k_scan1<<<NB_SCAN, 1024>>>();
    k_scan2<<<1, 128>>>();
    k_scan3<<<NB_SCAN, 1024>>>();
    k_scatter<<<(EE + 255) / 256, 256>>>(ei);
    k_mlp<<<(NN + 63) / 64, 256, SMEM_MLP_FLOATS * 4>>>(x, w1, b1, w2, b2, w3, b3, wx, bx);
    k_gather<<<(NN * 32 + 255) / 256, 256>>>(beta);
    k_final<<<(NN + 63) / 64, 256, SMEM_FIN_FLOATS * 4>>>(wg1, bg1, wg2, bg2, wf, bf, wc, bc, out);
}